// round 13
// baseline (speedup 1.0000x reference)
#include <cuda_runtime.h>
#include <cuda_fp16.h>
#include <math.h>
#include <stdint.h>

#define BS_TOK 16384
#define DIM    1024
#define NEXP   8
#define KTOK   2048
#define DDIM   4096

// GEMM tiling: 128x128 CTA tile, 8 warps (2 x 4), 64x32 warp tile, fp16 inputs
// 2 CTAs/SM (16 warps/SM).
#define BM 128
#define BN 128
#define BK 64                          // fp16 elements per chunk (128 B)
#define STAGES 3
#define KS 72                          // 64 k + 8 pad (halves); row = 144 B
#define A_STAGE_H (BM * KS)            // 9216 halves
#define B_STAGE_H (BN * KS)            // 9216 halves
#define STAGE_H (A_STAGE_H + B_STAGE_H)
#define SMEM_BYTES (STAGES * STAGE_H * 2)   // 110592 B

// ---------------- scratch (device globals; allocation-free rule) ----------
__device__ __align__(16) __half g_norm_h[(size_t)BS_TOK * DIM];       // 32 MiB
__device__ __align__(16) __half g_h1_h[(size_t)NEXP * KTOK * DDIM];   // 128 MiB
__device__ __align__(16) __half g_w1_h[(size_t)DIM * DIM];            // 2 MiB
__device__ __align__(16) __half g_fc1_h[(size_t)NEXP * DDIM * DIM];   // 64 MiB
__device__ __align__(16) __half g_fc2_h[(size_t)NEXP * DIM * DDIM];   // 64 MiB
__device__ __align__(16) float g_y[(size_t)NEXP * KTOK * DIM];        // 64 MiB (K half 0)
__device__ __align__(16) float g_y2[(size_t)NEXP * KTOK * DIM];       // 64 MiB (K half 1)
__device__ __align__(16) __half g_c1_h[(size_t)BS_TOK * DIM];         // 32 MiB
__device__ float g_zerobias[DIM];                                     // zero-initialized
__device__ float g_scores[(size_t)BS_TOK * NEXP];
__device__ int   g_kidx[NEXP * KTOK];
__device__ float g_kscore[NEXP * KTOK];
__device__ int   g_slot[(size_t)BS_TOK * NEXP];                       // token -> slot or -1
__device__ float g_lacc;

// ---------------- stream/event resources (created pre-main; no device mem) --
static cudaStream_t g_s1, g_s2;
static cudaEvent_t g_e0, g_eln, g_etop, g_ecf1, g_e1, g_e2;
static const bool g_res_init = [] {
    cudaStreamCreateWithFlags(&g_s1, cudaStreamNonBlocking);
    cudaStreamCreateWithFlags(&g_s2, cudaStreamNonBlocking);
    cudaEventCreateWithFlags(&g_e0,   cudaEventDisableTiming);
    cudaEventCreateWithFlags(&g_eln,  cudaEventDisableTiming);
    cudaEventCreateWithFlags(&g_etop, cudaEventDisableTiming);
    cudaEventCreateWithFlags(&g_ecf1, cudaEventDisableTiming);
    cudaEventCreateWithFlags(&g_e1,   cudaEventDisableTiming);
    cudaEventCreateWithFlags(&g_e2,   cudaEventDisableTiming);
    return true;
}();

// ---------------- helpers --------------------------------------------------
__device__ __forceinline__ float warpSum(float v) {
#pragma unroll
    for (int o = 16; o; o >>= 1) v += __shfl_xor_sync(0xffffffffu, v, o);
    return v;
}

__device__ __forceinline__ float tanh_fast(float x) {
    float y;
    asm("tanh.approx.f32 %0, %1;" : "=f"(y) : "f"(x));
    return y;
}

// fast gelu for GEMM epilogues only (selection path keeps exact tanhf)
__device__ __forceinline__ float gelu_tanh(float x) {
    float x3 = x * x * x;
    float t = tanh_fast(0.7978845608028654f * (x + 0.044715f * x3));
    return 0.5f * x * (1.f + t);
}

__device__ __forceinline__ uint32_t smem_u32(const void* p) {
    uint32_t a;
    asm("{ .reg .u64 t; cvta.to.shared.u64 t, %1; cvt.u32.u64 %0, t; }"
        : "=r"(a) : "l"(p));
    return a;
}

__device__ __forceinline__ void cp16(uint32_t saddr, const void* g) {
    asm volatile("cp.async.cg.shared.global [%0], [%1], 16;"
                 :: "r"(saddr), "l"(g) : "memory");
}

__device__ __forceinline__ void ldsm_x4(uint32_t* r, uint32_t saddr) {
    asm volatile("ldmatrix.sync.aligned.m8n8.x4.shared.b16 {%0,%1,%2,%3}, [%4];"
                 : "=r"(r[0]), "=r"(r[1]), "=r"(r[2]), "=r"(r[3]) : "r"(saddr));
}

__device__ __forceinline__ void mma_f16(float* c, const uint32_t* a, const uint32_t* b) {
    asm volatile(
        "mma.sync.aligned.m16n8k16.row.col.f32.f16.f16.f32 "
        "{%0,%1,%2,%3}, {%4,%5,%6,%7}, {%8,%9}, {%0,%1,%2,%3};"
        : "+f"(c[0]), "+f"(c[1]), "+f"(c[2]), "+f"(c[3])
        : "r"(a[0]), "r"(a[1]), "r"(a[2]), "r"(a[3]), "r"(b[0]), "r"(b[1]));
}

// ---------------- fp32 -> fp16 convert (weights, once per launch) -----------
__global__ void f32to16_kernel(const float* __restrict__ src,
                               __half* __restrict__ dst, long n4) {
    long i = (long)blockIdx.x * blockDim.x + threadIdx.x;
    long stride = (long)gridDim.x * blockDim.x;
    for (; i < n4; i += stride) {
        float4 v = ((const float4*)src)[i];
        ((__half2*)dst)[i * 2]     = __floats2half2_rn(v.x, v.y);
        ((__half2*)dst)[i * 2 + 1] = __floats2half2_rn(v.z, v.w);
    }
}

// ---------------- fp16 tensor-core GEMM body ---------------------------------
// C[M,N] = A[M,0:K] @ B[N,0:K]^T, row strides lda/ldb (elements), fp32 accum.
// OUTK: 0 = fp32 store, 1 = fp16 store, 2 = fp32 store scaled by ksc[row].
template <int GATHER_A, int GELU, int OUTK>
__device__ __forceinline__ void tc_gemm_body(
    const __half* __restrict__ A, int K, int lda,
    const __half* __restrict__ B, int ldb,
    const float* __restrict__ bias,
    void* __restrict__ Cout, int N,
    const int* __restrict__ gidx, const float* __restrict__ ksc)
{
    extern __shared__ __half smh[];
    __shared__ int s_rows[BM];

    const int tid = threadIdx.x;
    const int wid = tid >> 5, lane = tid & 31;
    const int gid = lane >> 2, tig = lane & 3;
    const int warp_m = (wid >> 2) * 64;     // 0 / 64
    const int warp_n = (wid & 3) * 32;      // 0 / 32 / 64 / 96
    const int brow = blockIdx.y * BM;
    const int bcol = blockIdx.x * BN;
    const uint32_t smem_base = smem_u32(smh);

    if (GATHER_A) {
        if (tid < BM) s_rows[tid] = gidx[brow + tid];
        __syncthreads();
    }

    float acc[4][4][4];
#pragma unroll
    for (int i = 0; i < 4; i++)
#pragma unroll
        for (int j = 0; j < 4; j++)
#pragma unroll
            for (int q = 0; q < 4; q++) acc[i][j][q] = 0.f;

    const int nck = K / BK;

    // ldmatrix per-lane base byte addresses (within stage 0)
    const uint32_t a_lane_base = smem_base +
        (uint32_t)(((warp_m + (lane & 15)) * KS + (lane >> 4) * 8) * 2);
    const uint32_t b_lane_base = smem_base + A_STAGE_H * 2 +
        (uint32_t)(((warp_n + (lane & 7) + ((lane >> 4) << 3)) * KS +
                    ((lane >> 3) & 1) * 8) * 2);

    // cp.async per stage: A 1024 granules (4/thr), B 1024 granules (4/thr)
    auto issue_stage = [&](int cidx) {
        const int k0 = cidx * BK;
        const uint32_t soff = (uint32_t)(cidx % STAGES) * (STAGE_H * 2);
#pragma unroll
        for (int i = 0; i < 4; i++) {
            int id = tid + i * 256;
            int row = id >> 3, kc = (id & 7) * 8;
            int ar = GATHER_A ? s_rows[row] : (brow + row);
            uint32_t dst = smem_base + soff + (uint32_t)(row * KS + kc) * 2;
            cp16(dst, A + (size_t)ar * lda + k0 + kc);
        }
#pragma unroll
        for (int i = 0; i < 4; i++) {
            int id = tid + i * 256;
            int row = id >> 3, kc = (id & 7) * 8;
            uint32_t dst = smem_base + soff + A_STAGE_H * 2 +
                           (uint32_t)(row * KS + kc) * 2;
            cp16(dst, B + (size_t)(bcol + row) * ldb + k0 + kc);
        }
    };

#pragma unroll
    for (int s = 0; s < STAGES - 1; s++) {
        issue_stage(s);
        asm volatile("cp.async.commit_group;" ::: "memory");
    }

#pragma unroll 1
    for (int c = 0; c < nck; ++c) {
        asm volatile("cp.async.wait_group %0;" :: "n"(STAGES - 2) : "memory");
        __syncthreads();

        int ncidx = c + STAGES - 1;
        if (ncidx < nck) issue_stage(ncidx);
        asm volatile("cp.async.commit_group;" ::: "memory");

        const uint32_t soff = (uint32_t)(c % STAGES) * (STAGE_H * 2);
        const uint32_t aaddr = a_lane_base + soff;
        const uint32_t baddr = b_lane_base + soff;

#pragma unroll
        for (int g = 0; g < 4; g++) {        // 4 k16 steps per BK=64 chunk
            uint32_t afr[4][4], bfr[2][4];
            const uint32_t ko = (uint32_t)g * 32;   // +16 halves per step
#pragma unroll
            for (int i = 0; i < 4; i++)
                ldsm_x4(afr[i], aaddr + ko + i * (16 * KS * 2));
#pragma unroll
            for (int p = 0; p < 2; p++)
                ldsm_x4(bfr[p], baddr + ko + p * (16 * KS * 2));
#pragma unroll
            for (int i = 0; i < 4; i++)
#pragma unroll
                for (int p = 0; p < 2; p++) {
                    mma_f16(acc[i][2 * p],     afr[i], &bfr[p][0]);
                    mma_f16(acc[i][2 * p + 1], afr[i], &bfr[p][2]);
                }
        }
    }

    // epilogue: c0,c1 are adjacent columns (2tig, 2tig+1)
#pragma unroll
    for (int i = 0; i < 4; i++) {
        int mrow0 = brow + warp_m + i * 16 + gid;
        int mrow1 = mrow0 + 8;
        float sc0 = 1.f, sc1 = 1.f;
        if (OUTK == 2) { sc0 = ksc[mrow0]; sc1 = ksc[mrow1]; }
#pragma unroll
        for (int j = 0; j < 4; j++) {
            int ncol = bcol + warp_n + j * 8 + tig * 2;
            float bi0 = bias[ncol];
            float bi1 = bias[ncol + 1];
            float v00 = acc[i][j][0] + bi0;
            float v01 = acc[i][j][1] + bi1;
            float v10 = acc[i][j][2] + bi0;
            float v11 = acc[i][j][3] + bi1;
            if (GELU) {
                v00 = gelu_tanh(v00); v01 = gelu_tanh(v01);
                v10 = gelu_tanh(v10); v11 = gelu_tanh(v11);
            }
            if (OUTK == 0) {
                float* C = (float*)Cout;
                *(float2*)&C[(size_t)mrow0 * N + ncol] = make_float2(v00, v01);
                *(float2*)&C[(size_t)mrow1 * N + ncol] = make_float2(v10, v11);
            } else if (OUTK == 1) {
                __half2* C = (__half2*)Cout;
                C[((size_t)mrow0 * N + ncol) >> 1] = __floats2half2_rn(v00, v01);
                C[((size_t)mrow1 * N + ncol) >> 1] = __floats2half2_rn(v10, v11);
            } else {
                float* C = (float*)Cout;
                *(float2*)&C[(size_t)mrow0 * N + ncol] = make_float2(v00 * sc0, v01 * sc0);
                *(float2*)&C[(size_t)mrow1 * N + ncol] = make_float2(v10 * sc1, v11 * sc1);
            }
        }
    }
}

// ---------------- GEMM wrappers ----------------------------------------------
__global__ __launch_bounds__(256, 2) void cap_tc(const float* __restrict__ b1) {
    tc_gemm_body<0, 1, 1>(g_norm_h, DIM, DIM, g_w1_h, DIM, b1, g_c1_h, DIM,
                          nullptr, nullptr);
}

__global__ __launch_bounds__(256, 2) void fc1_tc(const float* __restrict__ b1s) {
    int z = blockIdx.z;
    tc_gemm_body<1, 1, 1>(g_norm_h, DIM, DIM,
                          g_fc1_h + (size_t)z * DDIM * DIM, DIM,
                          b1s + (size_t)z * DDIM,
                          g_h1_h + (size_t)z * KTOK * DDIM, DDIM,
                          g_kidx + z * KTOK, nullptr);
}

// split-K: grid.z = 2*NEXP; each half does K=DDIM/2, partials to g_y / g_y2.
__global__ __launch_bounds__(256, 2) void fc2_tc(const float* __restrict__ b2s) {
    int zz = blockIdx.z;
    int z = zz >> 1, half = zz & 1;
    const float* bias = half ? g_zerobias : (b2s + (size_t)z * DIM);
    float* outbuf = (half ? g_y2 : g_y) + (size_t)z * KTOK * DIM;
    tc_gemm_body<0, 0, 2>(
        g_h1_h + (size_t)z * KTOK * DDIM + half * (DDIM / 2), DDIM / 2, DDIM,
        g_fc2_h + (size_t)z * DIM * DDIM + half * (DDIM / 2), DDIM,
        bias, outbuf, DIM,
        nullptr, g_kscore + z * KTOK);
}

// ---------------- gather: out = x + sum of selected expert output partials -----
__global__ __launch_bounds__(256) void gather_kernel(
    const float* __restrict__ x, float* __restrict__ out)
{
    int token = blockIdx.x;
    int t = threadIdx.x;                     // 256 threads = 1024 dims / 4
    __shared__ int s_slot[NEXP];
    if (t < NEXP) s_slot[t] = g_slot[(size_t)token * NEXP + t];
    __syncthreads();

    float4 v = ((const float4*)(x + (size_t)token * DIM))[t];
#pragma unroll
    for (int n = 0; n < NEXP; n++) {
        int sl = s_slot[n];
        if (sl >= 0) {
            size_t base = ((size_t)n * KTOK + sl) * DIM;
            float4 y1 = ((const float4*)(g_y  + base))[t];
            float4 y2 = ((const float4*)(g_y2 + base))[t];
            v.x += y1.x + y2.x; v.y += y1.y + y2.y;
            v.z += y1.z + y2.z; v.w += y1.w + y2.w;
        }
    }
    ((float4*)(out + (size_t)token * DIM))[t] = v;
}

// ---------------- fused LayerNorm + gate scores --------------------------------
__global__ __launch_bounds__(256) void ln_gate_kernel(
    const float* __restrict__ x, const float* __restrict__ g,
    const float* __restrict__ bparam, const float* __restrict__ gW)
{
    int row = blockIdx.x;
    int t = threadIdx.x, lane = t & 31, w = t >> 5;
    const float4* xr = (const float4*)(x + (size_t)row * DIM);
    float4 v = xr[t];

    __shared__ float red[8];
    __shared__ float sMean, sRstd;

    float s = v.x + v.y + v.z + v.w;
    s = warpSum(s);
    if (lane == 0) red[w] = s;
    __syncthreads();
    if (t == 0) {
        float tot = 0;
#pragma unroll
        for (int i = 0; i < 8; i++) tot += red[i];
        sMean = tot * (1.f / DIM);
    }
    __syncthreads();
    float mu = sMean;
    float d0 = v.x - mu, d1 = v.y - mu, d2 = v.z - mu, d3 = v.w - mu;
    float s2 = d0 * d0 + d1 * d1 + d2 * d2 + d3 * d3;
    s2 = warpSum(s2);
    __syncthreads();
    if (lane == 0) red[w] = s2;
    __syncthreads();
    if (t == 0) {
        float tot = 0;
#pragma unroll
        for (int i = 0; i < 8; i++) tot += red[i];
        sRstd = rsqrtf(tot * (1.f / DIM) + 1e-5f);
    }
    __syncthreads();
    float rstd = sRstd;

    float4 gv = ((const float4*)g)[t];
    float4 bv = ((const float4*)bparam)[t];
    float4 nv;
    nv.x = d0 * rstd * gv.x + bv.x;
    nv.y = d1 * rstd * gv.y + bv.y;
    nv.z = d2 * rstd * gv.z + bv.z;
    nv.w = d3 * rstd * gv.w + bv.w;

    // gate scores from EXACT fp32 values (selection must match reference)
    float acc[NEXP];
#pragma unroll
    for (int n = 0; n < NEXP; n++) {
        float4 wv = ((const float4*)(gW + (size_t)n * DIM))[t];
        float a = nv.x * wv.x + nv.y * wv.y + nv.z * wv.z + nv.w * wv.w;
        acc[n] = warpSum(a);
    }

    // store norm as fp16 (RNE) — only consumed by fp16 GEMMs
    __half2* dst = (__half2*)(g_norm_h + (size_t)row * DIM);
    dst[t * 2]     = __floats2half2_rn(nv.x, nv.y);
    dst[t * 2 + 1] = __floats2half2_rn(nv.z, nv.w);

    __shared__ float sacc[8][NEXP];
    if (lane == 0) {
#pragma unroll
        for (int n = 0; n < NEXP; n++) sacc[w][n] = acc[n];
    }
    __syncthreads();
    if (t < NEXP) {
        float tot = 0;
#pragma unroll
        for (int i = 0; i < 8; i++) tot += sacc[i][t];
        g_scores[(size_t)row * NEXP + t] = 0.5f * (tanhf(tot) + 1.f);
    }
}

// ---------------- per-expert top-k via radix select ----------------------------
__global__ __launch_bounds__(256) void topk_kernel() {
    int n = blockIdx.x;
    __shared__ unsigned int hist[256];
    __shared__ unsigned int s_prefix;
    __shared__ int s_remk;
    __shared__ int s_cnt;

    if (n == 0 && threadIdx.x == 0) g_lacc = 0.f;   // zero loss accum (precedes loss)

    for (int i = threadIdx.x; i < BS_TOK; i += blockDim.x)
        g_slot[(size_t)i * NEXP + n] = -1;
    if (threadIdx.x == 0) s_cnt = 0;
    __syncthreads();

    unsigned int prefix = 0;
    int remk = KTOK;
    for (int pass = 0; pass < 4; pass++) {
        int shift = 24 - 8 * pass;
        for (int i = threadIdx.x; i < 256; i += blockDim.x) hist[i] = 0;
        __syncthreads();
        unsigned int himask = (pass == 0) ? 0u : (0xFFFFFFFFu << (shift + 8));
        unsigned int hipref = (pass == 0) ? 0u : (prefix << (shift + 8));
        for (int i = threadIdx.x; i < BS_TOK; i += blockDim.x) {
            unsigned int key = __float_as_uint(g_scores[(size_t)i * NEXP + n]);
            if ((key & himask) == hipref) atomicAdd(&hist[(key >> shift) & 255u], 1u);
        }
        __syncthreads();
        if (threadIdx.x == 0) {
            int cum = 0;
            for (int b = 255; b >= 0; b--) {
                int c = (int)hist[b];
                if (cum + c >= remk) {
                    s_prefix = (prefix << 8) | (unsigned)b;
                    s_remk = remk - cum;
                    break;
                }
                cum += c;
            }
        }
        __syncthreads();
        prefix = s_prefix;
        remk = s_remk;
        __syncthreads();
    }
    unsigned int kth = prefix;

    for (int i = threadIdx.x; i < BS_TOK; i += blockDim.x) {
        unsigned int key = __float_as_uint(g_scores[(size_t)i * NEXP + n]);
        bool sel = false;
        if (key > kth) sel = true;
        else if (key == kth) {
            int rank = 0;
            for (int j = 0; j < i; j++)
                if (__float_as_uint(g_scores[(size_t)j * NEXP + n]) == kth) rank++;
            sel = (rank < remk);
        }
        if (sel) {
            int slot = atomicAdd(&s_cnt, 1);
            g_kidx[n * KTOK + slot] = i;
            g_kscore[n * KTOK + slot] = __uint_as_float(key);
            g_slot[(size_t)i * NEXP + n] = slot;
        }
    }
}

// ---------------- logits + softplus loss reduction -----------------------------
__global__ __launch_bounds__(256) void loss_kernel(
    const float* __restrict__ W2, const float* __restrict__ b2)
{
    int lane = threadIdx.x & 31, w = threadIdx.x >> 5;
    int row = blockIdx.x * 8 + w;
    const __half* r = g_c1_h + (size_t)row * DIM;
    float a[NEXP];
#pragma unroll
    for (int n = 0; n < NEXP; n++) a[n] = 0.f;
    for (int d = lane; d < DIM; d += 32) {
        float v = __half2float(r[d]);
#pragma unroll
        for (int n = 0; n < NEXP; n++) a[n] += v * W2[n * DIM + d];
    }
#pragma unroll
    for (int n = 0; n < NEXP; n++) a[n] = warpSum(a[n]);

    __shared__ float wpart[8];
    if (lane == 0) {
        float part = 0.f;
#pragma unroll
        for (int n = 0; n < NEXP; n++) {
            float l = a[n] + b2[n];
            float sp = fmaxf(l, 0.f) + log1pf(expf(-fabsf(l)));
            float m = (g_slot[(size_t)row * NEXP + n] >= 0) ? 1.f : 0.f;
            part += sp - l * m;
        }
        wpart[w] = part;
    }
    __syncthreads();
    if (threadIdx.x == 0) {
        float s = 0.f;
#pragma unroll
        for (int i = 0; i < 8; i++) s += wpart[i];
        atomicAdd(&g_lacc, s);
    }
}

// ---------------- finalize scalar loss ------------------------------------------
__global__ void finalize_kernel(float* __restrict__ dst) {
    *dst = g_lacc * (1.f / ((float)BS_TOK * (float)NEXP));
}

// ---------------- launch ----------------------------------------------------------
extern "C" void kernel_launch(void* const* d_in, const int* in_sizes, int n_in,
                              void* d_out, int out_size) {
    const float* x     = (const float*)d_in[0];
    const float* ln_g  = (const float*)d_in[1];
    const float* ln_b  = (const float*)d_in[2];
    const float* gateW = (const float*)d_in[3];
    const float* cpW1  = (const float*)d_in[4];
    const float* cpb1  = (const float*)d_in[5];
    const float* cpW2  = (const float*)d_in[6];
    const float* cpb2  = (const float*)d_in[7];
    const float* fc1s  = (const float*)d_in[8];
    const float* b1s   = (const float*)d_in[9];
    const float* fc2s  = (const float*)d_in[10];
    const float* b2s   = (const float*)d_in[11];
    float* out = (float*)d_out;
    (void)g_res_init;

    cudaFuncSetAttribute(cap_tc, cudaFuncAttributeMaxDynamicSharedMemorySize, SMEM_BYTES);
    cudaFuncSetAttribute(fc1_tc, cudaFuncAttributeMaxDynamicSharedMemorySize, SMEM_BYTES);
    cudaFuncSetAttribute(fc2_tc, cudaFuncAttributeMaxDynamicSharedMemorySize, SMEM_BYTES);

    __half* w1h;  cudaGetSymbolAddress((void**)&w1h,  g_w1_h);
    __half* f1h;  cudaGetSymbolAddress((void**)&f1h,  g_fc1_h);
    __half* f2h;  cudaGetSymbolAddress((void**)&f2h,  g_fc2_h);

    // fork point for side streams
    cudaEventRecord(g_e0, 0);

    // main stream: ln (1), topk (2) — selection critical path starts immediately
    ln_gate_kernel<<<BS_TOK, 256>>>(x, ln_g, ln_b, gateW);                   // 1
    cudaEventRecord(g_eln, 0);
    topk_kernel<<<NEXP, 256>>>();                                            // 2
    cudaEventRecord(g_etop, 0);

    // side stream s2: fc1 weight conversion (overlaps ln+topk), then fc2 conv
    cudaStreamWaitEvent(g_s2, g_e0, 0);
    f32to16_kernel<<<2048, 256, 0, g_s2>>>(fc1s, f1h, (long)NEXP * DDIM * DIM / 4); // 3
    cudaEventRecord(g_ecf1, g_s2);

    // main stream: fc1 (4th submitted kernel -> ncu target)
    cudaStreamWaitEvent(0, g_ecf1, 0);
    fc1_tc<<<dim3(DDIM / BN, KTOK / BM, NEXP), 256, SMEM_BYTES>>>(b1s);      // 4

    // s2 continues: fc2 weight conversion during fc1
    f32to16_kernel<<<2048, 256, 0, g_s2>>>(fc2s, f2h, (long)NEXP * DIM * DDIM / 4);
    cudaEventRecord(g_e2, g_s2);

    // side stream s1: capacity path — cap needs only ln (g_norm_h), loss needs topk
    cudaStreamWaitEvent(g_s1, g_eln, 0);
    f32to16_kernel<<<512, 256, 0, g_s1>>>(cpW1, w1h, (long)DIM * DIM / 4);
    cap_tc<<<dim3(DIM / BN, BS_TOK / BM, 1), 256, SMEM_BYTES, g_s1>>>(cpb1);
    cudaStreamWaitEvent(g_s1, g_etop, 0);
    loss_kernel<<<BS_TOK / 8, 256, 0, g_s1>>>(cpW2, cpb2);
    cudaEventRecord(g_e1, g_s1);

    // main stream: fc2 split-K2 (partials into g_y/g_y2), gather, finalize
    cudaStreamWaitEvent(0, g_e2, 0);
    fc2_tc<<<dim3(DIM / BN, KTOK / BM, NEXP * 2), 256, SMEM_BYTES>>>(b2s);
    gather_kernel<<<BS_TOK, 256>>>(x, out);
    cudaStreamWaitEvent(0, g_e1, 0);
    finalize_kernel<<<1, 1>>>(out + (out_size - 1));
}

// round 14
// speedup vs baseline: 1.0489x; 1.0489x over previous
#include <cuda_runtime.h>
#include <cuda_fp16.h>
#include <math.h>
#include <stdint.h>

#define BS_TOK 16384
#define DIM    1024
#define NEXP   8
#define KTOK   2048
#define DDIM   4096

// GEMM tiling: 128x128 CTA tile, 8 warps (2 x 4), 64x32 warp tile, fp16 inputs
// 2 CTAs/SM (16 warps/SM).
#define BM 128
#define BN 128
#define BK 64                          // fp16 elements per chunk (128 B)
#define STAGES 3
#define KS 72                          // 64 k + 8 pad (halves); row = 144 B
#define A_STAGE_H (BM * KS)            // 9216 halves
#define B_STAGE_H (BN * KS)            // 9216 halves
#define STAGE_H (A_STAGE_H + B_STAGE_H)
#define SMEM_BYTES (STAGES * STAGE_H * 2)   // 110592 B

// ---------------- scratch (device globals; allocation-free rule) ----------
__device__ __align__(16) __half g_norm_h[(size_t)BS_TOK * DIM];       // 32 MiB
__device__ __align__(16) __half g_h1_h[(size_t)NEXP * KTOK * DDIM];   // 128 MiB
__device__ __align__(16) __half g_w1_h[(size_t)DIM * DIM];            // 2 MiB
__device__ __align__(16) __half g_fc1_h[(size_t)NEXP * DDIM * DIM];   // 64 MiB
__device__ __align__(16) __half g_fc2_h[(size_t)NEXP * DIM * DDIM];   // 64 MiB
__device__ __align__(16) __half g_y_h[(size_t)NEXP * KTOK * DIM];     // 32 MiB
__device__ __align__(16) __half g_c1_h[(size_t)BS_TOK * DIM];         // 32 MiB
__device__ float g_scores[(size_t)BS_TOK * NEXP];
__device__ int   g_kidx[NEXP * KTOK];
__device__ float g_kscore[NEXP * KTOK];
__device__ int   g_slot[(size_t)BS_TOK * NEXP];                       // token -> slot or -1
__device__ float g_lacc;

// ---------------- stream/event resources (created pre-main; no device mem) --
static cudaStream_t g_s1, g_s2;
static cudaEvent_t g_e0, g_eln, g_etop, g_ecf1, g_e1, g_e2;
static const bool g_res_init = [] {
    cudaStreamCreateWithFlags(&g_s1, cudaStreamNonBlocking);
    cudaStreamCreateWithFlags(&g_s2, cudaStreamNonBlocking);
    cudaEventCreateWithFlags(&g_e0,   cudaEventDisableTiming);
    cudaEventCreateWithFlags(&g_eln,  cudaEventDisableTiming);
    cudaEventCreateWithFlags(&g_etop, cudaEventDisableTiming);
    cudaEventCreateWithFlags(&g_ecf1, cudaEventDisableTiming);
    cudaEventCreateWithFlags(&g_e1,   cudaEventDisableTiming);
    cudaEventCreateWithFlags(&g_e2,   cudaEventDisableTiming);
    return true;
}();

// ---------------- helpers --------------------------------------------------
__device__ __forceinline__ float warpSum(float v) {
#pragma unroll
    for (int o = 16; o; o >>= 1) v += __shfl_xor_sync(0xffffffffu, v, o);
    return v;
}

__device__ __forceinline__ float tanh_fast(float x) {
    float y;
    asm("tanh.approx.f32 %0, %1;" : "=f"(y) : "f"(x));
    return y;
}

// fast gelu for GEMM epilogues only (selection path keeps exact tanhf)
__device__ __forceinline__ float gelu_tanh(float x) {
    float x3 = x * x * x;
    float t = tanh_fast(0.7978845608028654f * (x + 0.044715f * x3));
    return 0.5f * x * (1.f + t);
}

__device__ __forceinline__ uint32_t smem_u32(const void* p) {
    uint32_t a;
    asm("{ .reg .u64 t; cvta.to.shared.u64 t, %1; cvt.u32.u64 %0, t; }"
        : "=r"(a) : "l"(p));
    return a;
}

__device__ __forceinline__ void cp16(uint32_t saddr, const void* g) {
    asm volatile("cp.async.cg.shared.global [%0], [%1], 16;"
                 :: "r"(saddr), "l"(g) : "memory");
}

__device__ __forceinline__ void ldsm_x4(uint32_t* r, uint32_t saddr) {
    asm volatile("ldmatrix.sync.aligned.m8n8.x4.shared.b16 {%0,%1,%2,%3}, [%4];"
                 : "=r"(r[0]), "=r"(r[1]), "=r"(r[2]), "=r"(r[3]) : "r"(saddr));
}

__device__ __forceinline__ void mma_f16(float* c, const uint32_t* a, const uint32_t* b) {
    asm volatile(
        "mma.sync.aligned.m16n8k16.row.col.f32.f16.f16.f32 "
        "{%0,%1,%2,%3}, {%4,%5,%6,%7}, {%8,%9}, {%0,%1,%2,%3};"
        : "+f"(c[0]), "+f"(c[1]), "+f"(c[2]), "+f"(c[3])
        : "r"(a[0]), "r"(a[1]), "r"(a[2]), "r"(a[3]), "r"(b[0]), "r"(b[1]));
}

// ---------------- fp32 -> fp16 convert (weights, once per launch) -----------
__global__ void f32to16_kernel(const float* __restrict__ src,
                               __half* __restrict__ dst, long n4) {
    long i = (long)blockIdx.x * blockDim.x + threadIdx.x;
    long stride = (long)gridDim.x * blockDim.x;
    for (; i < n4; i += stride) {
        float4 v = ((const float4*)src)[i];
        ((__half2*)dst)[i * 2]     = __floats2half2_rn(v.x, v.y);
        ((__half2*)dst)[i * 2 + 1] = __floats2half2_rn(v.z, v.w);
    }
}

// ---------------- fp16 tensor-core GEMM body ---------------------------------
// C[M,N] = A[M,0:K] @ B[N,0:K]^T, row strides lda/ldb (elements), fp32 accum.
// OUTK: 1 = fp16 store, 2 = fp16 store scaled by ksc[row].
template <int GATHER_A, int GELU, int OUTK>
__device__ __forceinline__ void tc_gemm_body(
    const __half* __restrict__ A, int K, int lda,
    const __half* __restrict__ B, int ldb,
    const float* __restrict__ bias,
    void* __restrict__ Cout, int N,
    const int* __restrict__ gidx, const float* __restrict__ ksc)
{
    extern __shared__ __half smh[];
    __shared__ int s_rows[BM];

    const int tid = threadIdx.x;
    const int wid = tid >> 5, lane = tid & 31;
    const int gid = lane >> 2, tig = lane & 3;
    const int warp_m = (wid >> 2) * 64;     // 0 / 64
    const int warp_n = (wid & 3) * 32;      // 0 / 32 / 64 / 96
    const int brow = blockIdx.y * BM;
    const int bcol = blockIdx.x * BN;
    const uint32_t smem_base = smem_u32(smh);

    if (GATHER_A) {
        if (tid < BM) s_rows[tid] = gidx[brow + tid];
        __syncthreads();
    }

    float acc[4][4][4];
#pragma unroll
    for (int i = 0; i < 4; i++)
#pragma unroll
        for (int j = 0; j < 4; j++)
#pragma unroll
            for (int q = 0; q < 4; q++) acc[i][j][q] = 0.f;

    const int nck = K / BK;

    // ldmatrix per-lane base byte addresses (within stage 0)
    const uint32_t a_lane_base = smem_base +
        (uint32_t)(((warp_m + (lane & 15)) * KS + (lane >> 4) * 8) * 2);
    const uint32_t b_lane_base = smem_base + A_STAGE_H * 2 +
        (uint32_t)(((warp_n + (lane & 7) + ((lane >> 4) << 3)) * KS +
                    ((lane >> 3) & 1) * 8) * 2);

    // cp.async per stage: A 1024 granules (4/thr), B 1024 granules (4/thr)
    auto issue_stage = [&](int cidx) {
        const int k0 = cidx * BK;
        const uint32_t soff = (uint32_t)(cidx % STAGES) * (STAGE_H * 2);
#pragma unroll
        for (int i = 0; i < 4; i++) {
            int id = tid + i * 256;
            int row = id >> 3, kc = (id & 7) * 8;
            int ar = GATHER_A ? s_rows[row] : (brow + row);
            uint32_t dst = smem_base + soff + (uint32_t)(row * KS + kc) * 2;
            cp16(dst, A + (size_t)ar * lda + k0 + kc);
        }
#pragma unroll
        for (int i = 0; i < 4; i++) {
            int id = tid + i * 256;
            int row = id >> 3, kc = (id & 7) * 8;
            uint32_t dst = smem_base + soff + A_STAGE_H * 2 +
                           (uint32_t)(row * KS + kc) * 2;
            cp16(dst, B + (size_t)(bcol + row) * ldb + k0 + kc);
        }
    };

#pragma unroll
    for (int s = 0; s < STAGES - 1; s++) {
        issue_stage(s);
        asm volatile("cp.async.commit_group;" ::: "memory");
    }

#pragma unroll 1
    for (int c = 0; c < nck; ++c) {
        asm volatile("cp.async.wait_group %0;" :: "n"(STAGES - 2) : "memory");
        __syncthreads();

        int ncidx = c + STAGES - 1;
        if (ncidx < nck) issue_stage(ncidx);
        asm volatile("cp.async.commit_group;" ::: "memory");

        const uint32_t soff = (uint32_t)(c % STAGES) * (STAGE_H * 2);
        const uint32_t aaddr = a_lane_base + soff;
        const uint32_t baddr = b_lane_base + soff;

#pragma unroll
        for (int g = 0; g < 4; g++) {        // 4 k16 steps per BK=64 chunk
            uint32_t afr[4][4], bfr[2][4];
            const uint32_t ko = (uint32_t)g * 32;   // +16 halves per step
#pragma unroll
            for (int i = 0; i < 4; i++)
                ldsm_x4(afr[i], aaddr + ko + i * (16 * KS * 2));
#pragma unroll
            for (int p = 0; p < 2; p++)
                ldsm_x4(bfr[p], baddr + ko + p * (16 * KS * 2));
#pragma unroll
            for (int i = 0; i < 4; i++)
#pragma unroll
                for (int p = 0; p < 2; p++) {
                    mma_f16(acc[i][2 * p],     afr[i], &bfr[p][0]);
                    mma_f16(acc[i][2 * p + 1], afr[i], &bfr[p][2]);
                }
        }
    }

    // epilogue: c0,c1 are adjacent columns (2tig, 2tig+1)
#pragma unroll
    for (int i = 0; i < 4; i++) {
        int mrow0 = brow + warp_m + i * 16 + gid;
        int mrow1 = mrow0 + 8;
        float sc0 = 1.f, sc1 = 1.f;
        if (OUTK == 2) { sc0 = ksc[mrow0]; sc1 = ksc[mrow1]; }
#pragma unroll
        for (int j = 0; j < 4; j++) {
            int ncol = bcol + warp_n + j * 8 + tig * 2;
            float bi0 = bias[ncol];
            float bi1 = bias[ncol + 1];
            float v00 = acc[i][j][0] + bi0;
            float v01 = acc[i][j][1] + bi1;
            float v10 = acc[i][j][2] + bi0;
            float v11 = acc[i][j][3] + bi1;
            if (GELU) {
                v00 = gelu_tanh(v00); v01 = gelu_tanh(v01);
                v10 = gelu_tanh(v10); v11 = gelu_tanh(v11);
            }
            if (OUTK == 2) {
                v00 *= sc0; v01 *= sc0; v10 *= sc1; v11 *= sc1;
            }
            __half2* C = (__half2*)Cout;
            C[((size_t)mrow0 * N + ncol) >> 1] = __floats2half2_rn(v00, v01);
            C[((size_t)mrow1 * N + ncol) >> 1] = __floats2half2_rn(v10, v11);
        }
    }
}

// ---------------- GEMM wrappers ----------------------------------------------
__global__ __launch_bounds__(256, 2) void cap_tc(const float* __restrict__ b1) {
    tc_gemm_body<0, 1, 1>(g_norm_h, DIM, DIM, g_w1_h, DIM, b1, g_c1_h, DIM,
                          nullptr, nullptr);
}

__global__ __launch_bounds__(256, 2) void fc1_tc(const float* __restrict__ b1s) {
    int z = blockIdx.z;
    tc_gemm_body<1, 1, 1>(g_norm_h, DIM, DIM,
                          g_fc1_h + (size_t)z * DDIM * DIM, DIM,
                          b1s + (size_t)z * DDIM,
                          g_h1_h + (size_t)z * KTOK * DDIM, DDIM,
                          g_kidx + z * KTOK, nullptr);
}

__global__ __launch_bounds__(256, 2) void fc2_tc(const float* __restrict__ b2s) {
    int z = blockIdx.z;
    tc_gemm_body<0, 0, 2>(g_h1_h + (size_t)z * KTOK * DDIM, DDIM, DDIM,
                          g_fc2_h + (size_t)z * DIM * DDIM, DDIM,
                          b2s + (size_t)z * DIM,
                          g_y_h + (size_t)z * KTOK * DIM, DIM,
                          nullptr, g_kscore + z * KTOK);
}

// ---------------- gather: out = x + sum of selected expert outputs -------------
__global__ __launch_bounds__(256) void gather_kernel(
    const float* __restrict__ x, float* __restrict__ out)
{
    int token = blockIdx.x;
    int t = threadIdx.x;                     // 256 threads = 1024 dims / 4
    __shared__ int s_slot[NEXP];
    if (t < NEXP) s_slot[t] = g_slot[(size_t)token * NEXP + t];
    __syncthreads();

    float4 v = ((const float4*)(x + (size_t)token * DIM))[t];
#pragma unroll
    for (int n = 0; n < NEXP; n++) {
        int sl = s_slot[n];
        if (sl >= 0) {
            const __half2* yp = (const __half2*)(g_y_h + ((size_t)n * KTOK + sl) * DIM);
            float2 y0 = __half22float2(yp[t * 2]);
            float2 y1 = __half22float2(yp[t * 2 + 1]);
            v.x += y0.x; v.y += y0.y; v.z += y1.x; v.w += y1.y;
        }
    }
    ((float4*)(out + (size_t)token * DIM))[t] = v;
}

// ---------------- fused LayerNorm + gate scores --------------------------------
__global__ __launch_bounds__(256) void ln_gate_kernel(
    const float* __restrict__ x, const float* __restrict__ g,
    const float* __restrict__ bparam, const float* __restrict__ gW)
{
    int row = blockIdx.x;
    int t = threadIdx.x, lane = t & 31, w = t >> 5;
    const float4* xr = (const float4*)(x + (size_t)row * DIM);
    float4 v = xr[t];

    __shared__ float red[8];
    __shared__ float sMean, sRstd;

    float s = v.x + v.y + v.z + v.w;
    s = warpSum(s);
    if (lane == 0) red[w] = s;
    __syncthreads();
    if (t == 0) {
        float tot = 0;
#pragma unroll
        for (int i = 0; i < 8; i++) tot += red[i];
        sMean = tot * (1.f / DIM);
    }
    __syncthreads();
    float mu = sMean;
    float d0 = v.x - mu, d1 = v.y - mu, d2 = v.z - mu, d3 = v.w - mu;
    float s2 = d0 * d0 + d1 * d1 + d2 * d2 + d3 * d3;
    s2 = warpSum(s2);
    __syncthreads();
    if (lane == 0) red[w] = s2;
    __syncthreads();
    if (t == 0) {
        float tot = 0;
#pragma unroll
        for (int i = 0; i < 8; i++) tot += red[i];
        sRstd = rsqrtf(tot * (1.f / DIM) + 1e-5f);
    }
    __syncthreads();
    float rstd = sRstd;

    float4 gv = ((const float4*)g)[t];
    float4 bv = ((const float4*)bparam)[t];
    float4 nv;
    nv.x = d0 * rstd * gv.x + bv.x;
    nv.y = d1 * rstd * gv.y + bv.y;
    nv.z = d2 * rstd * gv.z + bv.z;
    nv.w = d3 * rstd * gv.w + bv.w;

    // gate scores from EXACT fp32 values (selection must match reference)
    float acc[NEXP];
#pragma unroll
    for (int n = 0; n < NEXP; n++) {
        float4 wv = ((const float4*)(gW + (size_t)n * DIM))[t];
        float a = nv.x * wv.x + nv.y * wv.y + nv.z * wv.z + nv.w * wv.w;
        acc[n] = warpSum(a);
    }

    // store norm as fp16 (RNE) — only consumed by fp16 GEMMs
    __half2* dst = (__half2*)(g_norm_h + (size_t)row * DIM);
    dst[t * 2]     = __floats2half2_rn(nv.x, nv.y);
    dst[t * 2 + 1] = __floats2half2_rn(nv.z, nv.w);

    __shared__ float sacc[8][NEXP];
    if (lane == 0) {
#pragma unroll
        for (int n = 0; n < NEXP; n++) sacc[w][n] = acc[n];
    }
    __syncthreads();
    if (t < NEXP) {
        float tot = 0;
#pragma unroll
        for (int i = 0; i < 8; i++) tot += sacc[i][t];
        g_scores[(size_t)row * NEXP + t] = 0.5f * (tanhf(tot) + 1.f);
    }
}

// ---------------- per-expert top-k via radix select (1024 threads) -------------
__global__ __launch_bounds__(1024) void topk_kernel() {
    int n = blockIdx.x;
    __shared__ unsigned int hist[256];
    __shared__ unsigned int s_prefix;
    __shared__ int s_remk;
    __shared__ int s_cnt;

    if (n == 0 && threadIdx.x == 0) g_lacc = 0.f;   // zero loss accum (precedes loss)

    for (int i = threadIdx.x; i < BS_TOK; i += blockDim.x)
        g_slot[(size_t)i * NEXP + n] = -1;
    if (threadIdx.x == 0) s_cnt = 0;
    __syncthreads();

    unsigned int prefix = 0;
    int remk = KTOK;
    for (int pass = 0; pass < 4; pass++) {
        int shift = 24 - 8 * pass;
        for (int i = threadIdx.x; i < 256; i += blockDim.x) hist[i] = 0;
        __syncthreads();
        unsigned int himask = (pass == 0) ? 0u : (0xFFFFFFFFu << (shift + 8));
        unsigned int hipref = (pass == 0) ? 0u : (prefix << (shift + 8));
        for (int i = threadIdx.x; i < BS_TOK; i += blockDim.x) {
            unsigned int key = __float_as_uint(g_scores[(size_t)i * NEXP + n]);
            if ((key & himask) == hipref) atomicAdd(&hist[(key >> shift) & 255u], 1u);
        }
        __syncthreads();
        if (threadIdx.x == 0) {
            int cum = 0;
            for (int b = 255; b >= 0; b--) {
                int c = (int)hist[b];
                if (cum + c >= remk) {
                    s_prefix = (prefix << 8) | (unsigned)b;
                    s_remk = remk - cum;
                    break;
                }
                cum += c;
            }
        }
        __syncthreads();
        prefix = s_prefix;
        remk = s_remk;
        __syncthreads();
    }
    unsigned int kth = prefix;

    for (int i = threadIdx.x; i < BS_TOK; i += blockDim.x) {
        unsigned int key = __float_as_uint(g_scores[(size_t)i * NEXP + n]);
        bool sel = false;
        if (key > kth) sel = true;
        else if (key == kth) {
            int rank = 0;
            for (int j = 0; j < i; j++)
                if (__float_as_uint(g_scores[(size_t)j * NEXP + n]) == kth) rank++;
            sel = (rank < remk);
        }
        if (sel) {
            int slot = atomicAdd(&s_cnt, 1);
            g_kidx[n * KTOK + slot] = i;
            g_kscore[n * KTOK + slot] = __uint_as_float(key);
            g_slot[(size_t)i * NEXP + n] = slot;
        }
    }
}

// ---------------- logits + softplus loss reduction -----------------------------
__global__ __launch_bounds__(256) void loss_kernel(
    const float* __restrict__ W2, const float* __restrict__ b2)
{
    int lane = threadIdx.x & 31, w = threadIdx.x >> 5;
    int row = blockIdx.x * 8 + w;
    const __half* r = g_c1_h + (size_t)row * DIM;
    float a[NEXP];
#pragma unroll
    for (int n = 0; n < NEXP; n++) a[n] = 0.f;
    for (int d = lane; d < DIM; d += 32) {
        float v = __half2float(r[d]);
#pragma unroll
        for (int n = 0; n < NEXP; n++) a[n] += v * W2[n * DIM + d];
    }
#pragma unroll
    for (int n = 0; n < NEXP; n++) a[n] = warpSum(a[n]);

    __shared__ float wpart[8];
    if (lane == 0) {
        float part = 0.f;
#pragma unroll
        for (int n = 0; n < NEXP; n++) {
            float l = a[n] + b2[n];
            float sp = fmaxf(l, 0.f) + log1pf(expf(-fabsf(l)));
            float m = (g_slot[(size_t)row * NEXP + n] >= 0) ? 1.f : 0.f;
            part += sp - l * m;
        }
        wpart[w] = part;
    }
    __syncthreads();
    if (threadIdx.x == 0) {
        float s = 0.f;
#pragma unroll
        for (int i = 0; i < 8; i++) s += wpart[i];
        atomicAdd(&g_lacc, s);
    }
}

// ---------------- finalize scalar loss ------------------------------------------
__global__ void finalize_kernel(float* __restrict__ dst) {
    *dst = g_lacc * (1.f / ((float)BS_TOK * (float)NEXP));
}

// ---------------- launch ----------------------------------------------------------
extern "C" void kernel_launch(void* const* d_in, const int* in_sizes, int n_in,
                              void* d_out, int out_size) {
    const float* x     = (const float*)d_in[0];
    const float* ln_g  = (const float*)d_in[1];
    const float* ln_b  = (const float*)d_in[2];
    const float* gateW = (const float*)d_in[3];
    const float* cpW1  = (const float*)d_in[4];
    const float* cpb1  = (const float*)d_in[5];
    const float* cpW2  = (const float*)d_in[6];
    const float* cpb2  = (const float*)d_in[7];
    const float* fc1s  = (const float*)d_in[8];
    const float* b1s   = (const float*)d_in[9];
    const float* fc2s  = (const float*)d_in[10];
    const float* b2s   = (const float*)d_in[11];
    float* out = (float*)d_out;
    (void)g_res_init;

    cudaFuncSetAttribute(cap_tc, cudaFuncAttributeMaxDynamicSharedMemorySize, SMEM_BYTES);
    cudaFuncSetAttribute(fc1_tc, cudaFuncAttributeMaxDynamicSharedMemorySize, SMEM_BYTES);
    cudaFuncSetAttribute(fc2_tc, cudaFuncAttributeMaxDynamicSharedMemorySize, SMEM_BYTES);

    __half* w1h;  cudaGetSymbolAddress((void**)&w1h,  g_w1_h);
    __half* f1h;  cudaGetSymbolAddress((void**)&f1h,  g_fc1_h);
    __half* f2h;  cudaGetSymbolAddress((void**)&f2h,  g_fc2_h);

    // fork point for side streams
    cudaEventRecord(g_e0, 0);

    // main stream: ln (1), topk (2) — selection critical path starts immediately
    ln_gate_kernel<<<BS_TOK, 256>>>(x, ln_g, ln_b, gateW);                   // 1
    cudaEventRecord(g_eln, 0);
    topk_kernel<<<NEXP, 1024>>>();                                           // 2
    cudaEventRecord(g_etop, 0);

    // side stream s2: fc1 weight conversion (overlaps ln+topk), then fc2 conv
    cudaStreamWaitEvent(g_s2, g_e0, 0);
    f32to16_kernel<<<2048, 256, 0, g_s2>>>(fc1s, f1h, (long)NEXP * DDIM * DIM / 4); // 3
    cudaEventRecord(g_ecf1, g_s2);

    // main stream: fc1 (4th submitted kernel -> ncu target)
    cudaStreamWaitEvent(0, g_ecf1, 0);
    fc1_tc<<<dim3(DDIM / BN, KTOK / BM, NEXP), 256, SMEM_BYTES>>>(b1s);      // 4

    // s2 continues: fc2 weight conversion during fc1
    f32to16_kernel<<<2048, 256, 0, g_s2>>>(fc2s, f2h, (long)NEXP * DIM * DDIM / 4);
    cudaEventRecord(g_e2, g_s2);

    // side stream s1: capacity path — cap needs only ln (g_norm_h), loss needs topk
    cudaStreamWaitEvent(g_s1, g_eln, 0);
    f32to16_kernel<<<512, 256, 0, g_s1>>>(cpW1, w1h, (long)DIM * DIM / 4);
    cap_tc<<<dim3(DIM / BN, BS_TOK / BM, 1), 256, SMEM_BYTES, g_s1>>>(cpb1);
    cudaStreamWaitEvent(g_s1, g_etop, 0);
    loss_kernel<<<BS_TOK / 8, 256, 0, g_s1>>>(cpW2, cpb2);
    cudaEventRecord(g_e1, g_s1);

    // main stream: fc2 (fp16 scaled stores into g_y_h), gather, finalize
    cudaStreamWaitEvent(0, g_e2, 0);
    fc2_tc<<<dim3(DIM / BN, KTOK / BM, NEXP), 256, SMEM_BYTES>>>(b2s);
    gather_kernel<<<BS_TOK, 256>>>(x, out);
    cudaStreamWaitEvent(0, g_e1, 0);
    finalize_kernel<<<1, 1>>>(out + (out_size - 1));
}

// round 15
// speedup vs baseline: 1.0530x; 1.0039x over previous
#include <cuda_runtime.h>
#include <cuda_fp16.h>
#include <math.h>
#include <stdint.h>

#define BS_TOK 16384
#define DIM    1024
#define NEXP   8
#define KTOK   2048
#define DDIM   4096

// GEMM tiling: 128x128 CTA tile, 8 warps (2 x 4), 64x32 warp tile, fp16 inputs
// 2 CTAs/SM (16 warps/SM).
#define BM 128
#define BN 128
#define BK 64                          // fp16 elements per chunk (128 B)
#define STAGES 3
#define KS 72                          // 64 k + 8 pad (halves); row = 144 B
#define A_STAGE_H (BM * KS)            // 9216 halves
#define B_STAGE_H (BN * KS)            // 9216 halves
#define STAGE_H (A_STAGE_H + B_STAGE_H)
#define SMEM_BYTES (STAGES * STAGE_H * 2)   // 110592 B

// ---------------- scratch (device globals; allocation-free rule) ----------
__device__ __align__(16) __half g_norm_h[(size_t)BS_TOK * DIM];       // 32 MiB
__device__ __align__(16) __half g_h1_h[(size_t)NEXP * KTOK * DDIM];   // 128 MiB
__device__ __align__(16) __half g_w1_h[(size_t)DIM * DIM];            // 2 MiB
__device__ __align__(16) __half g_fc1_h[(size_t)NEXP * DDIM * DIM];   // 64 MiB
__device__ __align__(16) __half g_fc2_h[(size_t)NEXP * DIM * DDIM];   // 64 MiB
__device__ __align__(16) __half g_y_h[(size_t)NEXP * KTOK * DIM];     // 32 MiB
__device__ __align__(16) __half g_c1_h[(size_t)BS_TOK * DIM];         // 32 MiB
__device__ float g_scores[(size_t)BS_TOK * NEXP];
__device__ int   g_kidx[NEXP * KTOK];
__device__ float g_kscore[NEXP * KTOK];
__device__ int   g_slot[(size_t)BS_TOK * NEXP];                       // token -> slot or -1
__device__ float g_lacc;

// ---------------- stream/event resources (created pre-main; no device mem) --
static cudaStream_t g_s1, g_s2, g_sx[NEXP];
static cudaEvent_t g_e0, g_eln, g_etop, g_ecf1, g_e1, g_e2, g_edone[NEXP];
static const bool g_res_init = [] {
    cudaStreamCreateWithFlags(&g_s1, cudaStreamNonBlocking);
    cudaStreamCreateWithFlags(&g_s2, cudaStreamNonBlocking);
    for (int z = 0; z < NEXP; z++)
        cudaStreamCreateWithFlags(&g_sx[z], cudaStreamNonBlocking);
    cudaEventCreateWithFlags(&g_e0,   cudaEventDisableTiming);
    cudaEventCreateWithFlags(&g_eln,  cudaEventDisableTiming);
    cudaEventCreateWithFlags(&g_etop, cudaEventDisableTiming);
    cudaEventCreateWithFlags(&g_ecf1, cudaEventDisableTiming);
    cudaEventCreateWithFlags(&g_e1,   cudaEventDisableTiming);
    cudaEventCreateWithFlags(&g_e2,   cudaEventDisableTiming);
    for (int z = 0; z < NEXP; z++)
        cudaEventCreateWithFlags(&g_edone[z], cudaEventDisableTiming);
    return true;
}();

// ---------------- helpers --------------------------------------------------
__device__ __forceinline__ float warpSum(float v) {
#pragma unroll
    for (int o = 16; o; o >>= 1) v += __shfl_xor_sync(0xffffffffu, v, o);
    return v;
}

__device__ __forceinline__ float tanh_fast(float x) {
    float y;
    asm("tanh.approx.f32 %0, %1;" : "=f"(y) : "f"(x));
    return y;
}

// fast gelu for GEMM epilogues only (selection path keeps exact tanhf)
__device__ __forceinline__ float gelu_tanh(float x) {
    float x3 = x * x * x;
    float t = tanh_fast(0.7978845608028654f * (x + 0.044715f * x3));
    return 0.5f * x * (1.f + t);
}

__device__ __forceinline__ uint32_t smem_u32(const void* p) {
    uint32_t a;
    asm("{ .reg .u64 t; cvta.to.shared.u64 t, %1; cvt.u32.u64 %0, t; }"
        : "=r"(a) : "l"(p));
    return a;
}

__device__ __forceinline__ void cp16(uint32_t saddr, const void* g) {
    asm volatile("cp.async.cg.shared.global [%0], [%1], 16;"
                 :: "r"(saddr), "l"(g) : "memory");
}

__device__ __forceinline__ void ldsm_x4(uint32_t* r, uint32_t saddr) {
    asm volatile("ldmatrix.sync.aligned.m8n8.x4.shared.b16 {%0,%1,%2,%3}, [%4];"
                 : "=r"(r[0]), "=r"(r[1]), "=r"(r[2]), "=r"(r[3]) : "r"(saddr));
}

__device__ __forceinline__ void mma_f16(float* c, const uint32_t* a, const uint32_t* b) {
    asm volatile(
        "mma.sync.aligned.m16n8k16.row.col.f32.f16.f16.f32 "
        "{%0,%1,%2,%3}, {%4,%5,%6,%7}, {%8,%9}, {%0,%1,%2,%3};"
        : "+f"(c[0]), "+f"(c[1]), "+f"(c[2]), "+f"(c[3])
        : "r"(a[0]), "r"(a[1]), "r"(a[2]), "r"(a[3]), "r"(b[0]), "r"(b[1]));
}

// ---------------- fp32 -> fp16 convert (weights, once per launch) -----------
__global__ void f32to16_kernel(const float* __restrict__ src,
                               __half* __restrict__ dst, long n4) {
    long i = (long)blockIdx.x * blockDim.x + threadIdx.x;
    long stride = (long)gridDim.x * blockDim.x;
    for (; i < n4; i += stride) {
        float4 v = ((const float4*)src)[i];
        ((__half2*)dst)[i * 2]     = __floats2half2_rn(v.x, v.y);
        ((__half2*)dst)[i * 2 + 1] = __floats2half2_rn(v.z, v.w);
    }
}

// ---------------- fp16 tensor-core GEMM body ---------------------------------
// C[M,N] = A[M,0:K] @ B[N,0:K]^T, row strides lda/ldb (elements), fp32 accum.
// OUTK: 1 = fp16 store, 2 = fp16 store scaled by ksc[row].
template <int GATHER_A, int GELU, int OUTK>
__device__ __forceinline__ void tc_gemm_body(
    const __half* __restrict__ A, int K, int lda,
    const __half* __restrict__ B, int ldb,
    const float* __restrict__ bias,
    void* __restrict__ Cout, int N,
    const int* __restrict__ gidx, const float* __restrict__ ksc)
{
    extern __shared__ __half smh[];
    __shared__ int s_rows[BM];

    const int tid = threadIdx.x;
    const int wid = tid >> 5, lane = tid & 31;
    const int gid = lane >> 2, tig = lane & 3;
    const int warp_m = (wid >> 2) * 64;     // 0 / 64
    const int warp_n = (wid & 3) * 32;      // 0 / 32 / 64 / 96
    const int brow = blockIdx.y * BM;
    const int bcol = blockIdx.x * BN;
    const uint32_t smem_base = smem_u32(smh);

    if (GATHER_A) {
        if (tid < BM) s_rows[tid] = gidx[brow + tid];
        __syncthreads();
    }

    float acc[4][4][4];
#pragma unroll
    for (int i = 0; i < 4; i++)
#pragma unroll
        for (int j = 0; j < 4; j++)
#pragma unroll
            for (int q = 0; q < 4; q++) acc[i][j][q] = 0.f;

    const int nck = K / BK;

    // ldmatrix per-lane base byte addresses (within stage 0)
    const uint32_t a_lane_base = smem_base +
        (uint32_t)(((warp_m + (lane & 15)) * KS + (lane >> 4) * 8) * 2);
    const uint32_t b_lane_base = smem_base + A_STAGE_H * 2 +
        (uint32_t)(((warp_n + (lane & 7) + ((lane >> 4) << 3)) * KS +
                    ((lane >> 3) & 1) * 8) * 2);

    // cp.async per stage: A 1024 granules (4/thr), B 1024 granules (4/thr)
    auto issue_stage = [&](int cidx) {
        const int k0 = cidx * BK;
        const uint32_t soff = (uint32_t)(cidx % STAGES) * (STAGE_H * 2);
#pragma unroll
        for (int i = 0; i < 4; i++) {
            int id = tid + i * 256;
            int row = id >> 3, kc = (id & 7) * 8;
            int ar = GATHER_A ? s_rows[row] : (brow + row);
            uint32_t dst = smem_base + soff + (uint32_t)(row * KS + kc) * 2;
            cp16(dst, A + (size_t)ar * lda + k0 + kc);
        }
#pragma unroll
        for (int i = 0; i < 4; i++) {
            int id = tid + i * 256;
            int row = id >> 3, kc = (id & 7) * 8;
            uint32_t dst = smem_base + soff + A_STAGE_H * 2 +
                           (uint32_t)(row * KS + kc) * 2;
            cp16(dst, B + (size_t)(bcol + row) * ldb + k0 + kc);
        }
    };

#pragma unroll
    for (int s = 0; s < STAGES - 1; s++) {
        issue_stage(s);
        asm volatile("cp.async.commit_group;" ::: "memory");
    }

#pragma unroll 1
    for (int c = 0; c < nck; ++c) {
        asm volatile("cp.async.wait_group %0;" :: "n"(STAGES - 2) : "memory");
        __syncthreads();

        int ncidx = c + STAGES - 1;
        if (ncidx < nck) issue_stage(ncidx);
        asm volatile("cp.async.commit_group;" ::: "memory");

        const uint32_t soff = (uint32_t)(c % STAGES) * (STAGE_H * 2);
        const uint32_t aaddr = a_lane_base + soff;
        const uint32_t baddr = b_lane_base + soff;

#pragma unroll
        for (int g = 0; g < 4; g++) {        // 4 k16 steps per BK=64 chunk
            uint32_t afr[4][4], bfr[2][4];
            const uint32_t ko = (uint32_t)g * 32;   // +16 halves per step
#pragma unroll
            for (int i = 0; i < 4; i++)
                ldsm_x4(afr[i], aaddr + ko + i * (16 * KS * 2));
#pragma unroll
            for (int p = 0; p < 2; p++)
                ldsm_x4(bfr[p], baddr + ko + p * (16 * KS * 2));
#pragma unroll
            for (int i = 0; i < 4; i++)
#pragma unroll
                for (int p = 0; p < 2; p++) {
                    mma_f16(acc[i][2 * p],     afr[i], &bfr[p][0]);
                    mma_f16(acc[i][2 * p + 1], afr[i], &bfr[p][2]);
                }
        }
    }

    // epilogue: c0,c1 are adjacent columns (2tig, 2tig+1)
#pragma unroll
    for (int i = 0; i < 4; i++) {
        int mrow0 = brow + warp_m + i * 16 + gid;
        int mrow1 = mrow0 + 8;
        float sc0 = 1.f, sc1 = 1.f;
        if (OUTK == 2) { sc0 = ksc[mrow0]; sc1 = ksc[mrow1]; }
#pragma unroll
        for (int j = 0; j < 4; j++) {
            int ncol = bcol + warp_n + j * 8 + tig * 2;
            float bi0 = bias[ncol];
            float bi1 = bias[ncol + 1];
            float v00 = acc[i][j][0] + bi0;
            float v01 = acc[i][j][1] + bi1;
            float v10 = acc[i][j][2] + bi0;
            float v11 = acc[i][j][3] + bi1;
            if (GELU) {
                v00 = gelu_tanh(v00); v01 = gelu_tanh(v01);
                v10 = gelu_tanh(v10); v11 = gelu_tanh(v11);
            }
            if (OUTK == 2) {
                v00 *= sc0; v01 *= sc0; v10 *= sc1; v11 *= sc1;
            }
            __half2* C = (__half2*)Cout;
            C[((size_t)mrow0 * N + ncol) >> 1] = __floats2half2_rn(v00, v01);
            C[((size_t)mrow1 * N + ncol) >> 1] = __floats2half2_rn(v10, v11);
        }
    }
}

// ---------------- GEMM wrappers ----------------------------------------------
__global__ __launch_bounds__(256, 2) void cap_tc(const float* __restrict__ b1) {
    tc_gemm_body<0, 1, 1>(g_norm_h, DIM, DIM, g_w1_h, DIM, b1, g_c1_h, DIM,
                          nullptr, nullptr);
}

// per-expert launches (z passed as argument; grid = (N/BN, M/BM, 1))
__global__ __launch_bounds__(256, 2) void fc1_tc(const float* __restrict__ b1s, int z) {
    tc_gemm_body<1, 1, 1>(g_norm_h, DIM, DIM,
                          g_fc1_h + (size_t)z * DDIM * DIM, DIM,
                          b1s + (size_t)z * DDIM,
                          g_h1_h + (size_t)z * KTOK * DDIM, DDIM,
                          g_kidx + z * KTOK, nullptr);
}

__global__ __launch_bounds__(256, 2) void fc2_tc(const float* __restrict__ b2s, int z) {
    tc_gemm_body<0, 0, 2>(g_h1_h + (size_t)z * KTOK * DDIM, DDIM, DDIM,
                          g_fc2_h + (size_t)z * DIM * DDIM, DDIM,
                          b2s + (size_t)z * DIM,
                          g_y_h + (size_t)z * KTOK * DIM, DIM,
                          nullptr, g_kscore + z * KTOK);
}

// ---------------- gather: out = x + sum of selected expert outputs -------------
__global__ __launch_bounds__(256) void gather_kernel(
    const float* __restrict__ x, float* __restrict__ out)
{
    int token = blockIdx.x;
    int t = threadIdx.x;                     // 256 threads = 1024 dims / 4
    __shared__ int s_slot[NEXP];
    if (t < NEXP) s_slot[t] = g_slot[(size_t)token * NEXP + t];
    __syncthreads();

    float4 v = ((const float4*)(x + (size_t)token * DIM))[t];
#pragma unroll
    for (int n = 0; n < NEXP; n++) {
        int sl = s_slot[n];
        if (sl >= 0) {
            const __half2* yp = (const __half2*)(g_y_h + ((size_t)n * KTOK + sl) * DIM);
            float2 y0 = __half22float2(yp[t * 2]);
            float2 y1 = __half22float2(yp[t * 2 + 1]);
            v.x += y0.x; v.y += y0.y; v.z += y1.x; v.w += y1.y;
        }
    }
    ((float4*)(out + (size_t)token * DIM))[t] = v;
}

// ---------------- fused LayerNorm + gate scores --------------------------------
__global__ __launch_bounds__(256) void ln_gate_kernel(
    const float* __restrict__ x, const float* __restrict__ g,
    const float* __restrict__ bparam, const float* __restrict__ gW)
{
    int row = blockIdx.x;
    int t = threadIdx.x, lane = t & 31, w = t >> 5;
    const float4* xr = (const float4*)(x + (size_t)row * DIM);
    float4 v = xr[t];

    __shared__ float red[8];
    __shared__ float sMean, sRstd;

    float s = v.x + v.y + v.z + v.w;
    s = warpSum(s);
    if (lane == 0) red[w] = s;
    __syncthreads();
    if (t == 0) {
        float tot = 0;
#pragma unroll
        for (int i = 0; i < 8; i++) tot += red[i];
        sMean = tot * (1.f / DIM);
    }
    __syncthreads();
    float mu = sMean;
    float d0 = v.x - mu, d1 = v.y - mu, d2 = v.z - mu, d3 = v.w - mu;
    float s2 = d0 * d0 + d1 * d1 + d2 * d2 + d3 * d3;
    s2 = warpSum(s2);
    __syncthreads();
    if (lane == 0) red[w] = s2;
    __syncthreads();
    if (t == 0) {
        float tot = 0;
#pragma unroll
        for (int i = 0; i < 8; i++) tot += red[i];
        sRstd = rsqrtf(tot * (1.f / DIM) + 1e-5f);
    }
    __syncthreads();
    float rstd = sRstd;

    float4 gv = ((const float4*)g)[t];
    float4 bv = ((const float4*)bparam)[t];
    float4 nv;
    nv.x = d0 * rstd * gv.x + bv.x;
    nv.y = d1 * rstd * gv.y + bv.y;
    nv.z = d2 * rstd * gv.z + bv.z;
    nv.w = d3 * rstd * gv.w + bv.w;

    // gate scores from EXACT fp32 values (selection must match reference)
    float acc[NEXP];
#pragma unroll
    for (int n = 0; n < NEXP; n++) {
        float4 wv = ((const float4*)(gW + (size_t)n * DIM))[t];
        float a = nv.x * wv.x + nv.y * wv.y + nv.z * wv.z + nv.w * wv.w;
        acc[n] = warpSum(a);
    }

    // store norm as fp16 (RNE) — only consumed by fp16 GEMMs
    __half2* dst = (__half2*)(g_norm_h + (size_t)row * DIM);
    dst[t * 2]     = __floats2half2_rn(nv.x, nv.y);
    dst[t * 2 + 1] = __floats2half2_rn(nv.z, nv.w);

    __shared__ float sacc[8][NEXP];
    if (lane == 0) {
#pragma unroll
        for (int n = 0; n < NEXP; n++) sacc[w][n] = acc[n];
    }
    __syncthreads();
    if (t < NEXP) {
        float tot = 0;
#pragma unroll
        for (int i = 0; i < 8; i++) tot += sacc[i][t];
        g_scores[(size_t)row * NEXP + t] = 0.5f * (tanhf(tot) + 1.f);
    }
}

// ---------------- per-expert top-k via radix select (1024 threads) -------------
__global__ __launch_bounds__(1024) void topk_kernel() {
    int n = blockIdx.x;
    __shared__ unsigned int hist[256];
    __shared__ unsigned int s_prefix;
    __shared__ int s_remk;
    __shared__ int s_cnt;

    if (n == 0 && threadIdx.x == 0) g_lacc = 0.f;   // zero loss accum (precedes loss)

    for (int i = threadIdx.x; i < BS_TOK; i += blockDim.x)
        g_slot[(size_t)i * NEXP + n] = -1;
    if (threadIdx.x == 0) s_cnt = 0;
    __syncthreads();

    unsigned int prefix = 0;
    int remk = KTOK;
    for (int pass = 0; pass < 4; pass++) {
        int shift = 24 - 8 * pass;
        for (int i = threadIdx.x; i < 256; i += blockDim.x) hist[i] = 0;
        __syncthreads();
        unsigned int himask = (pass == 0) ? 0u : (0xFFFFFFFFu << (shift + 8));
        unsigned int hipref = (pass == 0) ? 0u : (prefix << (shift + 8));
        for (int i = threadIdx.x; i < BS_TOK; i += blockDim.x) {
            unsigned int key = __float_as_uint(g_scores[(size_t)i * NEXP + n]);
            if ((key & himask) == hipref) atomicAdd(&hist[(key >> shift) & 255u], 1u);
        }
        __syncthreads();
        if (threadIdx.x == 0) {
            int cum = 0;
            for (int b = 255; b >= 0; b--) {
                int c = (int)hist[b];
                if (cum + c >= remk) {
                    s_prefix = (prefix << 8) | (unsigned)b;
                    s_remk = remk - cum;
                    break;
                }
                cum += c;
            }
        }
        __syncthreads();
        prefix = s_prefix;
        remk = s_remk;
        __syncthreads();
    }
    unsigned int kth = prefix;

    for (int i = threadIdx.x; i < BS_TOK; i += blockDim.x) {
        unsigned int key = __float_as_uint(g_scores[(size_t)i * NEXP + n]);
        bool sel = false;
        if (key > kth) sel = true;
        else if (key == kth) {
            int rank = 0;
            for (int j = 0; j < i; j++)
                if (__float_as_uint(g_scores[(size_t)j * NEXP + n]) == kth) rank++;
            sel = (rank < remk);
        }
        if (sel) {
            int slot = atomicAdd(&s_cnt, 1);
            g_kidx[n * KTOK + slot] = i;
            g_kscore[n * KTOK + slot] = __uint_as_float(key);
            g_slot[(size_t)i * NEXP + n] = slot;
        }
    }
}

// ---------------- logits + softplus loss reduction -----------------------------
__global__ __launch_bounds__(256) void loss_kernel(
    const float* __restrict__ W2, const float* __restrict__ b2)
{
    int lane = threadIdx.x & 31, w = threadIdx.x >> 5;
    int row = blockIdx.x * 8 + w;
    const __half* r = g_c1_h + (size_t)row * DIM;
    float a[NEXP];
#pragma unroll
    for (int n = 0; n < NEXP; n++) a[n] = 0.f;
    for (int d = lane; d < DIM; d += 32) {
        float v = __half2float(r[d]);
#pragma unroll
        for (int n = 0; n < NEXP; n++) a[n] += v * W2[n * DIM + d];
    }
#pragma unroll
    for (int n = 0; n < NEXP; n++) a[n] = warpSum(a[n]);

    __shared__ float wpart[8];
    if (lane == 0) {
        float part = 0.f;
#pragma unroll
        for (int n = 0; n < NEXP; n++) {
            float l = a[n] + b2[n];
            float sp = fmaxf(l, 0.f) + log1pf(expf(-fabsf(l)));
            float m = (g_slot[(size_t)row * NEXP + n] >= 0) ? 1.f : 0.f;
            part += sp - l * m;
        }
        wpart[w] = part;
    }
    __syncthreads();
    if (threadIdx.x == 0) {
        float s = 0.f;
#pragma unroll
        for (int i = 0; i < 8; i++) s += wpart[i];
        atomicAdd(&g_lacc, s);
    }
}

// ---------------- finalize scalar loss ------------------------------------------
__global__ void finalize_kernel(float* __restrict__ dst) {
    *dst = g_lacc * (1.f / ((float)BS_TOK * (float)NEXP));
}

// ---------------- launch ----------------------------------------------------------
extern "C" void kernel_launch(void* const* d_in, const int* in_sizes, int n_in,
                              void* d_out, int out_size) {
    const float* x     = (const float*)d_in[0];
    const float* ln_g  = (const float*)d_in[1];
    const float* ln_b  = (const float*)d_in[2];
    const float* gateW = (const float*)d_in[3];
    const float* cpW1  = (const float*)d_in[4];
    const float* cpb1  = (const float*)d_in[5];
    const float* cpW2  = (const float*)d_in[6];
    const float* cpb2  = (const float*)d_in[7];
    const float* fc1s  = (const float*)d_in[8];
    const float* b1s   = (const float*)d_in[9];
    const float* fc2s  = (const float*)d_in[10];
    const float* b2s   = (const float*)d_in[11];
    float* out = (float*)d_out;
    (void)g_res_init;

    cudaFuncSetAttribute(cap_tc, cudaFuncAttributeMaxDynamicSharedMemorySize, SMEM_BYTES);
    cudaFuncSetAttribute(fc1_tc, cudaFuncAttributeMaxDynamicSharedMemorySize, SMEM_BYTES);
    cudaFuncSetAttribute(fc2_tc, cudaFuncAttributeMaxDynamicSharedMemorySize, SMEM_BYTES);

    __half* w1h;  cudaGetSymbolAddress((void**)&w1h,  g_w1_h);
    __half* f1h;  cudaGetSymbolAddress((void**)&f1h,  g_fc1_h);
    __half* f2h;  cudaGetSymbolAddress((void**)&f2h,  g_fc2_h);

    // fork point for side streams
    cudaEventRecord(g_e0, 0);

    // main stream: ln (1), topk (2) — selection critical path starts immediately
    ln_gate_kernel<<<BS_TOK, 256>>>(x, ln_g, ln_b, gateW);                   // 1
    cudaEventRecord(g_eln, 0);
    topk_kernel<<<NEXP, 1024>>>();                                           // 2
    cudaEventRecord(g_etop, 0);

    // side stream s2: fc1 weight conversion (overlaps ln+topk)
    cudaStreamWaitEvent(g_s2, g_e0, 0);
    f32to16_kernel<<<2048, 256, 0, g_s2>>>(fc1s, f1h, (long)NEXP * DDIM * DIM / 4); // 3
    cudaEventRecord(g_ecf1, g_s2);

    // per-expert streams: fc1_z -> fc2_z (in-stream order). fc1_z0 is the
    // 4th submitted kernel (ncu target).
    for (int z = 0; z < NEXP; z++) {
        cudaStreamWaitEvent(g_sx[z], g_ecf1, 0);
        cudaStreamWaitEvent(g_sx[z], g_etop, 0);
        fc1_tc<<<dim3(DDIM / BN, KTOK / BM, 1), 256, SMEM_BYTES, g_sx[z]>>>(b1s, z);
    }

    // s2 continues: fc2 weight conversion during fc1 wave
    f32to16_kernel<<<2048, 256, 0, g_s2>>>(fc2s, f2h, (long)NEXP * DIM * DDIM / 4);
    cudaEventRecord(g_e2, g_s2);

    for (int z = 0; z < NEXP; z++) {
        cudaStreamWaitEvent(g_sx[z], g_e2, 0);
        fc2_tc<<<dim3(DIM / BN, KTOK / BM, 1), 256, SMEM_BYTES, g_sx[z]>>>(b2s, z);
        cudaEventRecord(g_edone[z], g_sx[z]);
    }

    // side stream s1: capacity path — cap needs only ln (g_norm_h), loss needs topk
    cudaStreamWaitEvent(g_s1, g_eln, 0);
    f32to16_kernel<<<512, 256, 0, g_s1>>>(cpW1, w1h, (long)DIM * DIM / 4);
    cap_tc<<<dim3(DIM / BN, BS_TOK / BM, 1), 256, SMEM_BYTES, g_s1>>>(cpb1);
    cudaStreamWaitEvent(g_s1, g_etop, 0);
    loss_kernel<<<BS_TOK / 8, 256, 0, g_s1>>>(cpW2, cpb2);
    cudaEventRecord(g_e1, g_s1);

    // main stream: gather after all experts, finalize after loss
    for (int z = 0; z < NEXP; z++) cudaStreamWaitEvent(0, g_edone[z], 0);
    gather_kernel<<<BS_TOK, 256>>>(x, out);
    cudaStreamWaitEvent(0, g_e1, 0);
    finalize_kernel<<<1, 1>>>(out + (out_size - 1));
}